// round 1
// baseline (speedup 1.0000x reference)
#include <cuda_runtime.h>
#include <cuda_bf16.h>

#define Bx 16
#define Nx 4096
#define Sx 1024
#define Kx 32
#define Dx 64
#define Px (Bx*Sx*Kx)   // 524288

// ---------------- device scratch (static, no allocation) ----------------
__device__ float g_centers[Bx*Sx*3];
__device__ int   g_gidx[Bx*Sx*Kx];
__device__ float g_ptsT[Bx*Nx*Dx];
__device__ float g_X0[68u*Px];     // 67 ch + 1 zero pad, channel-major
__device__ float g_Y1[64u*Px];
__device__ float g_Y2[64u*Px];
__device__ float g_Y3[128u*Px];
__device__ float g_sum[384];
__device__ float g_sumsq[384];
__device__ float g_mu[384];
__device__ float g_a[384];

// ---------------- utility ----------------
__global__ void zero_stats_kernel() {
    int t = blockIdx.x*256 + threadIdx.x;
    if (t < 384) { g_sum[t] = 0.f; g_sumsq[t] = 0.f; }
}

// transpose points (B,64,N) -> ptsT (B,N,64)
__global__ void transpose_kernel(const float* __restrict__ pts) {
    __shared__ float tile[32][33];
    int b = blockIdx.z;
    int n0 = blockIdx.x * 32;
    int d0 = blockIdx.y * 32;
    int tx = threadIdx.x, ty = threadIdx.y;
    tile[ty][tx] = pts[((size_t)b*Dx + d0 + ty)*Nx + n0 + tx];
    __syncthreads();
    g_ptsT[((size_t)b*Nx + n0 + ty)*Dx + d0 + tx] = tile[tx][ty];
}

// ---------------- FPS: one block per batch ----------------
__global__ __launch_bounds__(256) void fps_kernel(const float* __restrict__ xyz,
                                                  float* __restrict__ out) {
    int b = blockIdx.x;
    int t = threadIdx.x;
    const float* xb = xyz + (size_t)b*3*Nx;

    float px[16], py[16], pz[16], dst[16];
#pragma unroll
    for (int i = 0; i < 16; i++) {
        int n = i*256 + t;
        px[i] = xb[n]; py[i] = xb[Nx+n]; pz[i] = xb[2*Nx+n];
        dst[i] = 1e10f;
    }

    __shared__ float sc[3];
    __shared__ float svals[8];
    __shared__ int   sidx[8];
    __shared__ int   sfar;

    int far = 0;
    for (int s = 0; s < Sx; s++) {
        if (t == 0) {
            sc[0] = __ldg(xb + far);
            sc[1] = __ldg(xb + Nx + far);
            sc[2] = __ldg(xb + 2*Nx + far);
        }
        __syncthreads();
        float cx = sc[0], cy = sc[1], cz = sc[2];
        if (t == 0) {
            out[b*3*Sx + s]        = cx;
            out[b*3*Sx + Sx + s]   = cy;
            out[b*3*Sx + 2*Sx + s] = cz;
            g_centers[(b*Sx + s)*3 + 0] = cx;
            g_centers[(b*Sx + s)*3 + 1] = cy;
            g_centers[(b*Sx + s)*3 + 2] = cz;
        }
        float best = -1.f; int bn = 0;
#pragma unroll
        for (int i = 0; i < 16; i++) {
            float dx = px[i]-cx, dy = py[i]-cy, dz = pz[i]-cz;
            float d = (dx*dx + dy*dy) + dz*dz;
            float nd = fminf(dst[i], d);
            dst[i] = nd;
            int n = i*256 + t;
            if (nd > best) { best = nd; bn = n; }  // ascending n: strict > keeps first max
        }
#pragma unroll
        for (int off = 16; off; off >>= 1) {
            float ov = __shfl_down_sync(0xffffffffu, best, off);
            int   on = __shfl_down_sync(0xffffffffu, bn,   off);
            if (ov > best || (ov == best && on < bn)) { best = ov; bn = on; }
        }
        int w = t >> 5;
        if ((t & 31) == 0) { svals[w] = best; sidx[w] = bn; }
        __syncthreads();
        if (t < 32) {
            float v = (t < 8) ? svals[t] : -1.f;
            int  n2 = (t < 8) ? sidx[t]  : 0;
#pragma unroll
            for (int off = 4; off; off >>= 1) {
                float ov = __shfl_down_sync(0xffffffffu, v,  off);
                int   on = __shfl_down_sync(0xffffffffu, n2, off);
                if (ov > v || (ov == v && on < n2)) { v = ov; n2 = on; }
            }
            if (t == 0) sfar = n2;
        }
        __syncthreads();
        far = sfar;
    }
}

// ---------------- ball query: one warp per centroid ----------------
__global__ __launch_bounds__(256) void qb_kernel(const float* __restrict__ xyz) {
    int blk = blockIdx.x;          // B * S/8 = 2048
    int b = blk >> 7;
    int w = threadIdx.x >> 5;
    int s = (blk & 127)*8 + w;
    int lane = threadIdx.x & 31;

    __shared__ int buf[8][32];
    const float* xb = xyz + (size_t)b*3*Nx;

    float cx = g_centers[(b*Sx+s)*3 + 0];
    float cy = g_centers[(b*Sx+s)*3 + 1];
    float cz = g_centers[(b*Sx+s)*3 + 2];
    float s2 = (cx*cx + cy*cy) + cz*cz;

    int cnt = 0;
    for (int base = 0; base < Nx; base += 32) {
        int n = base + lane;
        float pxv = __ldg(xb + n);
        float pyv = __ldg(xb + Nx + n);
        float pzv = __ldg(xb + 2*Nx + n);
        float dot = (cx*pxv + cy*pyv) + cz*pzv;
        float d2  = (pxv*pxv + pyv*pyv) + pzv*pzv;
        float d = -2.f*dot; d += s2; d += d2;
        bool in = !(d > 0.01f);
        unsigned m = __ballot_sync(0xffffffffu, in);
        if (in) {
            int pos = cnt + __popc(m & ((1u << lane) - 1u));
            if (pos < Kx) buf[w][pos] = n;
        }
        cnt += __popc(m);
        if (cnt >= Kx) break;
    }
    __syncwarp();
    int nv = cnt < Kx ? cnt : Kx;    // nv >= 1 always (centroid is its own neighbor)
    int first = buf[w][0];
    int v = (lane < nv) ? buf[w][lane] : first;
    g_gidx[(b*Sx + s)*Kx + lane] = v;
}

// ---------------- gather: build X0 (68 x P, channel-major) ----------------
__global__ __launch_bounds__(256) void gather_kernel(const float* __restrict__ xyz) {
    int p = blockIdx.x*256 + threadIdx.x;
    int bs = p >> 5;               // b*S + s
    int b = bs >> 10;
    int idx = g_gidx[p];
    float cx = g_centers[bs*3 + 0];
    float cy = g_centers[bs*3 + 1];
    float cz = g_centers[bs*3 + 2];
    const float* xb = xyz + (size_t)b*3*Nx;
    g_X0[0u*Px + p] = __ldg(xb + idx)        - cx;
    g_X0[1u*Px + p] = __ldg(xb + Nx + idx)   - cy;
    g_X0[2u*Px + p] = __ldg(xb + 2*Nx + idx) - cz;
    const float4* pt = reinterpret_cast<const float4*>(g_ptsT + ((size_t)b*Nx + idx)*Dx);
#pragma unroll
    for (int j = 0; j < 16; j++) {
        float4 v = pt[j];
        g_X0[(size_t)(3 + 4*j + 0)*Px + p] = v.x;
        g_X0[(size_t)(3 + 4*j + 1)*Px + p] = v.y;
        g_X0[(size_t)(3 + 4*j + 2)*Px + p] = v.z;
        g_X0[(size_t)(3 + 4*j + 3)*Px + p] = v.w;
    }
    g_X0[67u*Px + p] = 0.f;
}

// ---------------- MLP layer: Y[o][p] = sum_c W[o][c] * act(X[c][p]) + bias ----
// act = identity (layer 1) or BN+ReLU from previous layer's stats.
// Also accumulates per-channel sum / sumsq of Y into global stats.
template<int CIN4, bool BN>
__global__ __launch_bounds__(256) void mlp_kernel(
    const float* __restrict__ X,
    const float* __restrict__ W, int ldw,
    const float* __restrict__ bias,
    const float* __restrict__ mu, const float* __restrict__ a,
    const float* __restrict__ beta,
    float* __restrict__ Y,
    float* __restrict__ gsum, float* __restrict__ gsq)
{
    constexpr int CINP = CIN4*4;
    __shared__ float4 s_w4[16*CIN4];
    __shared__ float  s_b[16];
    __shared__ float  s_sum[16], s_sq[16];
    __shared__ float  s_mu[CINP], s_a[CINP], s_beta[CINP];

    int tid = threadIdx.x;
    int o0 = blockIdx.y * 16;

    float* s_w = reinterpret_cast<float*>(s_w4);
    for (int i = tid; i < 16*CINP; i += 256) {
        int o = i / CINP, c = i % CINP;
        s_w[o*CINP + c] = (c < ldw) ? W[(o0 + o)*ldw + c] : 0.f;
    }
    if (tid < 16) { s_b[tid] = bias[o0 + tid]; s_sum[tid] = 0.f; s_sq[tid] = 0.f; }
    if (BN) {
        for (int i = tid; i < CINP; i += 256) {
            s_mu[i] = mu[i]; s_a[i] = a[i]; s_beta[i] = beta[i];
        }
    }
    __syncthreads();

    int p = blockIdx.x*256 + tid;
    float acc[16];
#pragma unroll
    for (int o = 0; o < 16; o++) acc[o] = 0.f;

#pragma unroll
    for (int c4 = 0; c4 < CIN4; c4++) {
        float xv[4];
#pragma unroll
        for (int j = 0; j < 4; j++) {
            int c = c4*4 + j;
            float v = X[(size_t)c*Px + p];
            if (BN) {
                v = (v - s_mu[c]) * s_a[c] + s_beta[c];
                v = fmaxf(v, 0.f);
            }
            xv[j] = v;
        }
#pragma unroll
        for (int o = 0; o < 16; o++) {
            float4 w4 = s_w4[o*CIN4 + c4];
            acc[o] = fmaf(w4.x, xv[0], acc[o]);
            acc[o] = fmaf(w4.y, xv[1], acc[o]);
            acc[o] = fmaf(w4.z, xv[2], acc[o]);
            acc[o] = fmaf(w4.w, xv[3], acc[o]);
        }
    }

    int lane = tid & 31;
#pragma unroll
    for (int o = 0; o < 16; o++) {
        float y = acc[o] + s_b[o];
        Y[(size_t)(o0 + o)*Px + p] = y;
        float s1 = y, sq = y*y;
#pragma unroll
        for (int off = 16; off; off >>= 1) {
            s1 += __shfl_down_sync(0xffffffffu, s1, off);
            sq += __shfl_down_sync(0xffffffffu, sq, off);
        }
        if (lane == 0) { atomicAdd(&s_sum[o], s1); atomicAdd(&s_sq[o], sq); }
    }
    __syncthreads();
    if (tid < 16) {
        atomicAdd(&gsum[o0 + tid], s_sum[tid]);
        atomicAdd(&gsq[o0 + tid],  s_sq[tid]);
    }
}

// ---------------- BN finalize ----------------
__global__ void bn_finalize_kernel(int layer, const float* __restrict__ gamma, int C) {
    int c = threadIdx.x;
    if (c < C) {
        float sm = g_sum[layer*128 + c];
        float sq = g_sumsq[layer*128 + c];
        float m = sm * (1.f/524288.f);          // 2^-19, exact
        float v = sq * (1.f/524288.f) - m*m;
        g_mu[layer*128 + c] = m;
        g_a[layer*128 + c]  = gamma[c] * rsqrtf(v + 1e-5f);
    }
}

// ---------------- final: BN+ReLU+max over group ----------------
__global__ __launch_bounds__(256) void max_kernel(const float* __restrict__ Y,
                                                  const float* __restrict__ mu,
                                                  const float* __restrict__ a,
                                                  const float* __restrict__ beta,
                                                  float* __restrict__ out) {
    int i = blockIdx.x*256 + threadIdx.x;   // over B*128*S = 2097152
    int b = i >> 17;
    int r = i & 131071;
    int c = r >> 10;
    int s = r & 1023;
    float m0 = mu[c], a0 = a[c], be = beta[c];
    const float4* yp = reinterpret_cast<const float4*>(Y + (size_t)c*Px + ((size_t)(b*Sx + s) << 5));
    float m = 0.f;   // ReLU floor
#pragma unroll
    for (int j = 0; j < 8; j++) {
        float4 y4 = yp[j];
        m = fmaxf(m, (y4.x - m0)*a0 + be);
        m = fmaxf(m, (y4.y - m0)*a0 + be);
        m = fmaxf(m, (y4.z - m0)*a0 + be);
        m = fmaxf(m, (y4.w - m0)*a0 + be);
    }
    out[16*3*1024 + i] = m;
}

// ---------------- launch ----------------
extern "C" void kernel_launch(void* const* d_in, const int* in_sizes, int n_in,
                              void* d_out, int out_size) {
    const float* xyz = (const float*)d_in[0];
    const float* pts = (const float*)d_in[1];
    const float* W0 = (const float*)d_in[2];
    const float* b0 = (const float*)d_in[3];
    const float* ga0 = (const float*)d_in[4];
    const float* be0 = (const float*)d_in[5];
    const float* W1 = (const float*)d_in[6];
    const float* b1 = (const float*)d_in[7];
    const float* ga1 = (const float*)d_in[8];
    const float* be1 = (const float*)d_in[9];
    const float* W2 = (const float*)d_in[10];
    const float* b2 = (const float*)d_in[11];
    const float* ga2 = (const float*)d_in[12];
    const float* be2 = (const float*)d_in[13];
    float* out = (float*)d_out;

    float *pX0, *pY1, *pY2, *pY3, *pSum, *pSq, *pMu, *pA;
    cudaGetSymbolAddress((void**)&pX0, g_X0);
    cudaGetSymbolAddress((void**)&pY1, g_Y1);
    cudaGetSymbolAddress((void**)&pY2, g_Y2);
    cudaGetSymbolAddress((void**)&pY3, g_Y3);
    cudaGetSymbolAddress((void**)&pSum, g_sum);
    cudaGetSymbolAddress((void**)&pSq, g_sumsq);
    cudaGetSymbolAddress((void**)&pMu, g_mu);
    cudaGetSymbolAddress((void**)&pA, g_a);

    zero_stats_kernel<<<2, 256>>>();
    transpose_kernel<<<dim3(Nx/32, Dx/32, Bx), dim3(32, 32)>>>(pts);
    fps_kernel<<<Bx, 256>>>(xyz, out);
    qb_kernel<<<Bx*Sx/8, 256>>>(xyz);
    gather_kernel<<<Px/256, 256>>>(xyz);

    // layer 1: 67(->68) -> 64, no input BN
    mlp_kernel<17, false><<<dim3(Px/256, 4), 256>>>(
        pX0, W0, 67, b0, nullptr, nullptr, nullptr, pY1, pSum + 0, pSq + 0);
    bn_finalize_kernel<<<1, 128>>>(0, ga0, 64);

    // layer 2: 64 -> 64, BN(layer0)+ReLU on input
    mlp_kernel<16, true><<<dim3(Px/256, 4), 256>>>(
        pY1, W1, 64, b1, pMu + 0, pA + 0, be0, pY2, pSum + 128, pSq + 128);
    bn_finalize_kernel<<<1, 128>>>(1, ga1, 64);

    // layer 3: 64 -> 128, BN(layer1)+ReLU on input
    mlp_kernel<16, true><<<dim3(Px/256, 8), 256>>>(
        pY2, W2, 64, b2, pMu + 128, pA + 128, be1, pY3, pSum + 256, pSq + 256);
    bn_finalize_kernel<<<1, 128>>>(2, ga2, 128);

    // BN(layer2)+ReLU + max over group -> output
    max_kernel<<<(Bx*128*Sx)/256, 256>>>(pY3, pMu + 256, pA + 256, be2, out);
}

// round 2
// speedup vs baseline: 1.2739x; 1.2739x over previous
#include <cuda_runtime.h>
#include <cuda_bf16.h>

#define Bx 16
#define Nx 4096
#define Sx 1024
#define Kx 32
#define Dx 64
#define Px (Bx*Sx*Kx)   // 524288

typedef unsigned long long ull;

// ---------------- device scratch (static, no allocation) ----------------
__device__ float g_centers[Bx*Sx*3];
__device__ int   g_gidx[Bx*Sx*Kx];
__device__ float g_ptsT[Bx*Nx*Dx];
__device__ float g_Y1[64u*Px];
__device__ float g_Y2[64u*Px];
__device__ float g_Y3[128u*Px];
__device__ float g_psum[1024];
__device__ float g_psq[1024];
__device__ float g_a[384];    // BN scale A = gamma*rsqrt(var+eps)
__device__ float g_bb[384];   // BN offset B = beta - mu*A

// ---------------- f32x2 helpers ----------------
__device__ __forceinline__ void ffma2(ull &acc, ull a, ull b) {
    asm("fma.rn.f32x2 %0, %1, %2, %0;" : "+l"(acc) : "l"(a), "l"(b));
}
__device__ __forceinline__ ull packf2(float lo, float hi) {
    ull r; asm("mov.b64 %0, {%1, %2};" : "=l"(r) : "f"(lo), "f"(hi)); return r;
}
__device__ __forceinline__ float2 unpackf2(ull v) {
    float lo, hi; asm("mov.b64 {%0, %1}, %2;" : "=f"(lo), "=f"(hi) : "l"(v));
    return make_float2(lo, hi);
}

// ---------------- transpose points (B,64,N) -> ptsT (B,N,64) ----------------
__global__ void transpose_kernel(const float* __restrict__ pts) {
    __shared__ float tile[32][33];
    int b = blockIdx.z;
    int n0 = blockIdx.x * 32;
    int d0 = blockIdx.y * 32;
    int tx = threadIdx.x, ty = threadIdx.y;
    tile[ty][tx] = pts[((size_t)b*Dx + d0 + ty)*Nx + n0 + tx];
    __syncthreads();
    g_ptsT[((size_t)b*Nx + n0 + ty)*Dx + d0 + tx] = tile[tx][ty];
}

// ---------------- FPS: one block per batch, ONE barrier per iter ----------------
__global__ __launch_bounds__(256) void fps_kernel(const float* __restrict__ xyz,
                                                  float* __restrict__ out) {
    int b = blockIdx.x;
    int t = threadIdx.x;
    int lane = t & 31, w = t >> 5;
    const float* xb = xyz + (size_t)b*3*Nx;

    float px[16], py[16], pz[16], dst[16];
#pragma unroll
    for (int i = 0; i < 16; i++) {
        int n = i*256 + t;
        px[i] = xb[n]; py[i] = xb[Nx+n]; pz[i] = xb[2*Nx+n];
        dst[i] = 1e10f;
    }

    __shared__ ull s_red[2][8];

    int far = 0;
    for (int s = 0; s < Sx; s++) {
        float cx = __ldg(xb + far);
        float cy = __ldg(xb + Nx + far);
        float cz = __ldg(xb + 2*Nx + far);
        if (t == 0) {
            out[b*3*Sx + s]        = cx;
            out[b*3*Sx + Sx + s]   = cy;
            out[b*3*Sx + 2*Sx + s] = cz;
            g_centers[(b*Sx + s)*3 + 0] = cx;
            g_centers[(b*Sx + s)*3 + 1] = cy;
            g_centers[(b*Sx + s)*3 + 2] = cz;
        }
        float best = -1.f; int bn = 0;
#pragma unroll
        for (int i = 0; i < 16; i++) {
            float dx = px[i]-cx, dy = py[i]-cy, dz = pz[i]-cz;
            float d = (dx*dx + dy*dy) + dz*dz;
            float nd = fminf(dst[i], d);
            dst[i] = nd;
            int n = i*256 + t;
            if (nd > best) { best = nd; bn = n; }  // ascending n: strict > keeps first max
        }
        // pack (dist, inverted index): max -> max dist, tie -> smallest index
        ull key = ((ull)__float_as_uint(best) << 32) | (unsigned)(0x7FFFFFFF - bn);
#pragma unroll
        for (int off = 16; off; off >>= 1) {
            ull o = __shfl_down_sync(0xffffffffu, key, off);
            if (o > key) key = o;
        }
        if (lane == 0) s_red[s & 1][w] = key;
        __syncthreads();
        ull k = (lane < 8) ? s_red[s & 1][lane] : 0ull;
#pragma unroll
        for (int off = 4; off; off >>= 1) {
            ull o = __shfl_down_sync(0xffffffffu, k, off);
            if (o > k) k = o;
        }
        k = __shfl_sync(0xffffffffu, k, 0);
        far = 0x7FFFFFFF - (int)(unsigned)(k & 0xFFFFFFFFull);
    }
}

// ---------------- ball query: one warp per centroid, 4 pts/thread ----------------
__global__ __launch_bounds__(256) void qb_kernel(const float* __restrict__ xyz) {
    int blk = blockIdx.x;          // B * S/8 = 2048
    int b = blk >> 7;
    int w = threadIdx.x >> 5;
    int s = (blk & 127)*8 + w;
    int lane = threadIdx.x & 31;

    __shared__ int buf[8][32];
    const float* xb = xyz + (size_t)b*3*Nx;

    float cx = g_centers[(b*Sx+s)*3 + 0];
    float cy = g_centers[(b*Sx+s)*3 + 1];
    float cz = g_centers[(b*Sx+s)*3 + 2];
    float s2 = (cx*cx + cy*cy) + cz*cz;

    int cnt = 0;
    for (int base = 0; base < Nx; base += 128) {
        int n0 = base + lane*4;
        float4 X4 = *reinterpret_cast<const float4*>(xb + n0);
        float4 Y4 = *reinterpret_cast<const float4*>(xb + Nx + n0);
        float4 Z4 = *reinterpret_cast<const float4*>(xb + 2*Nx + n0);
        unsigned msk = 0;
        {
            float dot = (cx*X4.x + cy*Y4.x) + cz*Z4.x;
            float d2  = (X4.x*X4.x + Y4.x*Y4.x) + Z4.x*Z4.x;
            float d = -2.f*dot; d += s2; d += d2;
            if (!(d > 0.01f)) msk |= 1u;
        }
        {
            float dot = (cx*X4.y + cy*Y4.y) + cz*Z4.y;
            float d2  = (X4.y*X4.y + Y4.y*Y4.y) + Z4.y*Z4.y;
            float d = -2.f*dot; d += s2; d += d2;
            if (!(d > 0.01f)) msk |= 2u;
        }
        {
            float dot = (cx*X4.z + cy*Y4.z) + cz*Z4.z;
            float d2  = (X4.z*X4.z + Y4.z*Y4.z) + Z4.z*Z4.z;
            float d = -2.f*dot; d += s2; d += d2;
            if (!(d > 0.01f)) msk |= 4u;
        }
        {
            float dot = (cx*X4.w + cy*Y4.w) + cz*Z4.w;
            float d2  = (X4.w*X4.w + Y4.w*Y4.w) + Z4.w*Z4.w;
            float d = -2.f*dot; d += s2; d += d2;
            if (!(d > 0.01f)) msk |= 8u;
        }
        int tc = __popc(msk);
        int inc = tc;
#pragma unroll
        for (int d = 1; d < 32; d <<= 1) {
            int v = __shfl_up_sync(0xffffffffu, inc, d);
            if (lane >= d) inc += v;
        }
        int excl = inc - tc;
        int total = __shfl_sync(0xffffffffu, inc, 31);
        int pos = cnt + excl;
#pragma unroll
        for (int j = 0; j < 4; j++) {
            if (msk & (1u << j)) { if (pos < Kx) buf[w][pos] = n0 + j; pos++; }
        }
        cnt += total;
        if (cnt >= Kx) break;
    }
    __syncwarp();
    int nv = cnt < Kx ? cnt : Kx;    // nv >= 1 always (centroid is its own neighbor)
    int first = buf[w][0];
    int v = (lane < nv) ? buf[w][lane] : first;
    g_gidx[(b*Sx + s)*Kx + lane] = v;
}

// ---------------- layer 1: fused gather + GEMM (FFMA2) ----------------
// channel order: 0..63 = points features, 64..66 = xyz-diff, 67 = zero pad
__global__ __launch_bounds__(256) void mlp1_kernel(const float* __restrict__ xyz,
                                                   const float* __restrict__ W,
                                                   const float* __restrict__ bias,
                                                   float* __restrict__ Y) {
    __shared__ float s_w[32*68];
    __shared__ float s_b[32];
    int tid = threadIdx.x;
    int o0 = blockIdx.y * 32;
    for (int i = tid; i < 32*68; i += 256) {
        int o = i / 68, c = i % 68;
        float wv;
        if (c < 64)      wv = W[(o0 + o)*67 + 3 + c];
        else if (c < 67) wv = W[(o0 + o)*67 + (c - 64)];
        else             wv = 0.f;
        s_w[i] = wv;
    }
    if (tid < 32) s_b[tid] = bias[o0 + tid];
    __syncthreads();

    size_t p = (size_t)(blockIdx.x*256 + tid) * 2;
    int bs = (int)(p >> 5);
    int b = bs >> 10;
    int idx0 = g_gidx[p], idx1 = g_gidx[p + 1];

    const ull* r0 = reinterpret_cast<const ull*>(g_ptsT + ((size_t)b*Nx + idx0)*Dx);
    const ull* r1 = reinterpret_cast<const ull*>(g_ptsT + ((size_t)b*Nx + idx1)*Dx);

    ull acc[32][2];
#pragma unroll
    for (int o = 0; o < 32; o++) { acc[o][0] = 0ull; acc[o][1] = 0ull; }

#pragma unroll 4
    for (int c2 = 0; c2 < 32; c2++) {
        ull v0 = r0[c2];
        ull v1 = r1[c2];
#pragma unroll
        for (int o = 0; o < 32; o++) {
            ull w2 = *reinterpret_cast<const ull*>(s_w + o*68 + 2*c2);
            ffma2(acc[o][0], w2, v0);
            ffma2(acc[o][1], w2, v1);
        }
    }

    // xyz-diff channels 64..67
    float cx = g_centers[bs*3 + 0];
    float cy = g_centers[bs*3 + 1];
    float cz = g_centers[bs*3 + 2];
    const float* xb = xyz + (size_t)b*3*Nx;
    float dx0 = __ldg(xb + idx0)        - cx;
    float dy0 = __ldg(xb + Nx + idx0)   - cy;
    float dz0 = __ldg(xb + 2*Nx + idx0) - cz;
    float dx1 = __ldg(xb + idx1)        - cx;
    float dy1 = __ldg(xb + Nx + idx1)   - cy;
    float dz1 = __ldg(xb + 2*Nx + idx1) - cz;
    ull va0 = packf2(dx0, dy0), vb0 = packf2(dz0, 0.f);
    ull va1 = packf2(dx1, dy1), vb1 = packf2(dz1, 0.f);
#pragma unroll
    for (int o = 0; o < 32; o++) {
        ull w2a = *reinterpret_cast<const ull*>(s_w + o*68 + 64);
        ull w2b = *reinterpret_cast<const ull*>(s_w + o*68 + 66);
        ffma2(acc[o][0], w2a, va0);
        ffma2(acc[o][0], w2b, vb0);
        ffma2(acc[o][1], w2a, va1);
        ffma2(acc[o][1], w2b, vb1);
    }

#pragma unroll
    for (int o = 0; o < 32; o++) {
        float2 a0 = unpackf2(acc[o][0]);
        float2 a1 = unpackf2(acc[o][1]);
        float2 r;
        r.x = a0.x + a0.y + s_b[o];
        r.y = a1.x + a1.y + s_b[o];
        *reinterpret_cast<float2*>(Y + (size_t)(o0 + o)*Px + p) = r;
    }
}

// ---------------- layers 2/3: BN+ReLU on input + GEMM (FFMA2) ----------------
__global__ __launch_bounds__(256) void mlp_bn_kernel(const float* __restrict__ X,
                                                     const float* __restrict__ W,
                                                     const float* __restrict__ bias,
                                                     const float* __restrict__ Aarr,
                                                     const float* __restrict__ Barr,
                                                     float* __restrict__ Y) {
    __shared__ float s_w[32*64];
    __shared__ float s_A[64], s_B[64];
    __shared__ float s_b[32];
    int tid = threadIdx.x;
    int o0 = blockIdx.y * 32;
    for (int i = tid; i < 32*64; i += 256) s_w[i] = W[o0*64 + i];
    if (tid < 64) { s_A[tid] = Aarr[tid]; s_B[tid] = Barr[tid]; }
    if (tid < 32) s_b[tid] = bias[o0 + tid];
    __syncthreads();

    size_t p = (size_t)(blockIdx.x*256 + tid) * 2;

    ull acc[32][2];
#pragma unroll
    for (int o = 0; o < 32; o++) { acc[o][0] = 0ull; acc[o][1] = 0ull; }

#pragma unroll 4
    for (int c2 = 0; c2 < 32; c2++) {
        int c = 2*c2;
        float2 xa = *reinterpret_cast<const float2*>(X + (size_t)c*Px + p);
        float2 xc = *reinterpret_cast<const float2*>(X + (size_t)(c+1)*Px + p);
        float A0 = s_A[c], B0 = s_B[c], A1 = s_A[c+1], B1 = s_B[c+1];
        float v00 = fmaxf(fmaf(xa.x, A0, B0), 0.f);
        float v01 = fmaxf(fmaf(xc.x, A1, B1), 0.f);
        float v10 = fmaxf(fmaf(xa.y, A0, B0), 0.f);
        float v11 = fmaxf(fmaf(xc.y, A1, B1), 0.f);
        ull v0 = packf2(v00, v01);
        ull v1 = packf2(v10, v11);
#pragma unroll
        for (int o = 0; o < 32; o++) {
            ull w2 = *reinterpret_cast<const ull*>(s_w + o*64 + c);
            ffma2(acc[o][0], w2, v0);
            ffma2(acc[o][1], w2, v1);
        }
    }

#pragma unroll
    for (int o = 0; o < 32; o++) {
        float2 a0 = unpackf2(acc[o][0]);
        float2 a1 = unpackf2(acc[o][1]);
        float2 r;
        r.x = a0.x + a0.y + s_b[o];
        r.y = a1.x + a1.y + s_b[o];
        *reinterpret_cast<float2*>(Y + (size_t)(o0 + o)*Px + p) = r;
    }
}

// ---------------- per-channel stats: deterministic partials ----------------
__global__ __launch_bounds__(256) void stats_kernel(const float* __restrict__ Y,
                                                    float* __restrict__ psum,
                                                    float* __restrict__ psq) {
    int c = blockIdx.x >> 3, seg = blockIdx.x & 7;
    const float4* base = reinterpret_cast<const float4*>(Y + (size_t)c*Px + (size_t)seg*65536);
    int t = threadIdx.x;
    float s = 0.f, q = 0.f;
#pragma unroll 4
    for (int i = 0; i < 64; i++) {
        float4 v = base[(size_t)i*256 + t];
        s += v.x + v.y + v.z + v.w;
        q += v.x*v.x + v.y*v.y + v.z*v.z + v.w*v.w;
    }
    int lane = t & 31, w = t >> 5;
#pragma unroll
    for (int off = 16; off; off >>= 1) {
        s += __shfl_down_sync(0xffffffffu, s, off);
        q += __shfl_down_sync(0xffffffffu, q, off);
    }
    __shared__ float ss[8], sq[8];
    if (lane == 0) { ss[w] = s; sq[w] = q; }
    __syncthreads();
    if (t == 0) {
        float S = 0.f, Q = 0.f;
#pragma unroll
        for (int k = 0; k < 8; k++) { S += ss[k]; Q += sq[k]; }
        psum[blockIdx.x] = S;
        psq[blockIdx.x]  = Q;
    }
}

// ---------------- BN finalize: A = gamma*rsqrt(var+eps), B = beta - mu*A ----
__global__ void finalize_kernel(int layer, const float* __restrict__ gamma,
                                const float* __restrict__ beta, int C) {
    int c = threadIdx.x;
    if (c >= C) return;
    float S = 0.f, Q = 0.f;
#pragma unroll
    for (int k = 0; k < 8; k++) { S += g_psum[c*8 + k]; Q += g_psq[c*8 + k]; }
    float m = S * (1.f/524288.f);          // 2^-19, exact
    float var = Q * (1.f/524288.f) - m*m;
    float A = gamma[c] * rsqrtf(var + 1e-5f);
    g_a[layer*128 + c]  = A;
    g_bb[layer*128 + c] = beta[c] - m*A;
}

// ---------------- final: BN+ReLU+max over group ----------------
__global__ __launch_bounds__(256) void max_kernel(const float* __restrict__ Y,
                                                  const float* __restrict__ A,
                                                  const float* __restrict__ B,
                                                  float* __restrict__ out) {
    int i = blockIdx.x*256 + threadIdx.x;   // over B*128*S = 2097152
    int b = i >> 17;
    int r = i & 131071;
    int c = r >> 10;
    int s = r & 1023;
    float a0 = A[c], b0 = B[c];
    const float4* yp = reinterpret_cast<const float4*>(Y + (size_t)c*Px + ((size_t)(b*Sx + s) << 5));
    float m = 0.f;   // ReLU floor
#pragma unroll
    for (int j = 0; j < 8; j++) {
        float4 y4 = yp[j];
        m = fmaxf(m, fmaf(y4.x, a0, b0));
        m = fmaxf(m, fmaf(y4.y, a0, b0));
        m = fmaxf(m, fmaf(y4.z, a0, b0));
        m = fmaxf(m, fmaf(y4.w, a0, b0));
    }
    out[16*3*1024 + i] = m;
}

// ---------------- launch ----------------
extern "C" void kernel_launch(void* const* d_in, const int* in_sizes, int n_in,
                              void* d_out, int out_size) {
    const float* xyz = (const float*)d_in[0];
    const float* pts = (const float*)d_in[1];
    const float* W0 = (const float*)d_in[2];
    const float* b0 = (const float*)d_in[3];
    const float* ga0 = (const float*)d_in[4];
    const float* be0 = (const float*)d_in[5];
    const float* W1 = (const float*)d_in[6];
    const float* b1 = (const float*)d_in[7];
    const float* ga1 = (const float*)d_in[8];
    const float* be1 = (const float*)d_in[9];
    const float* W2 = (const float*)d_in[10];
    const float* b2 = (const float*)d_in[11];
    const float* ga2 = (const float*)d_in[12];
    const float* be2 = (const float*)d_in[13];
    float* out = (float*)d_out;

    float *pY1, *pY2, *pY3, *pA, *pB, *pPS, *pPQ;
    cudaGetSymbolAddress((void**)&pY1, g_Y1);
    cudaGetSymbolAddress((void**)&pY2, g_Y2);
    cudaGetSymbolAddress((void**)&pY3, g_Y3);
    cudaGetSymbolAddress((void**)&pA, g_a);
    cudaGetSymbolAddress((void**)&pB, g_bb);
    cudaGetSymbolAddress((void**)&pPS, g_psum);
    cudaGetSymbolAddress((void**)&pPQ, g_psq);

    fps_kernel<<<Bx, 256>>>(xyz, out);
    qb_kernel<<<Bx*Sx/8, 256>>>(xyz);
    transpose_kernel<<<dim3(Nx/32, Dx/32, Bx), dim3(32, 32)>>>(pts);

    // layer 1: gather fused, 67(->68) -> 64
    mlp1_kernel<<<dim3(Px/512, 2), 256>>>(xyz, W0, b0, pY1);
    stats_kernel<<<64*8, 256>>>(pY1, pPS, pPQ);
    finalize_kernel<<<1, 128>>>(0, ga0, be0, 64);

    // layer 2: 64 -> 64, BN(layer0)+ReLU on input
    mlp_bn_kernel<<<dim3(Px/512, 2), 256>>>(pY1, W1, b1, pA + 0, pB + 0, pY2);
    stats_kernel<<<64*8, 256>>>(pY2, pPS, pPQ);
    finalize_kernel<<<1, 128>>>(1, ga1, be1, 64);

    // layer 3: 64 -> 128, BN(layer1)+ReLU on input
    mlp_bn_kernel<<<dim3(Px/512, 4), 256>>>(pY2, W2, b2, pA + 128, pB + 128, pY3);
    stats_kernel<<<128*8, 256>>>(pY3, pPS, pPQ);
    finalize_kernel<<<1, 128>>>(2, ga2, be2, 128);

    // BN(layer2)+ReLU + max over group -> output
    max_kernel<<<(Bx*128*Sx)/256, 256>>>(pY3, pA + 256, pB + 256, out);
}